// round 1
// baseline (speedup 1.0000x reference)
#include <cuda_runtime.h>
#include <math.h>

// Global accumulators (no allocation allowed)
__device__ double       g_sum;
__device__ unsigned int g_cnt;
__device__ unsigned int g_wpos;

__global__ void sbl_init_kernel() {
    g_sum  = 0.0;
    g_cnt  = 0u;
    g_wpos = 0u;
}

#define ROWS_PER_BLOCK 256

__global__ void __launch_bounds__(ROWS_PER_BLOCK)
sbl_main_kernel(const float* __restrict__ pts,
                const float* __restrict__ bbox,
                const float* __restrict__ w,
                int N)
{
    __shared__ float s_pts[ROWS_PER_BLOCK * 18];
    __shared__ float s_box[ROWS_PER_BLOCK * 8];

    const int tid  = threadIdx.x;
    const int base = blockIdx.x * ROWS_PER_BLOCK;
    const int nrows = min(ROWS_PER_BLOCK, N - base);

    // ---- Coalesced staging: pts ----
    {
        const int tot = nrows * 18;
        const int n4  = tot >> 2;                 // float4 count
        const float4* __restrict__ src4 = (const float4*)(pts + (size_t)base * 18);
        float4* dst4 = (float4*)s_pts;
        for (int i = tid; i < n4; i += ROWS_PER_BLOCK) dst4[i] = src4[i];
        for (int i = (n4 << 2) + tid; i < tot; i += ROWS_PER_BLOCK)
            s_pts[i] = pts[(size_t)base * 18 + i];
    }
    // ---- Coalesced staging: bbox ----
    {
        const int tot = nrows * 8;                // always divisible by 4
        const int n4  = tot >> 2;
        const float4* __restrict__ src4 = (const float4*)(bbox + (size_t)base * 8);
        float4* dst4 = (float4*)s_box;
        for (int i = tid; i < n4; i += ROWS_PER_BLOCK) dst4[i] = src4[i];
    }
    __syncthreads();

    float        dist_sum = 0.0f;
    unsigned int cnt      = 0u;
    unsigned int wp       = 0u;

    if (tid < nrows) {
        const float* P = s_pts + tid * 18;
        const float* B = s_box + tid * 8;

        const float vx0 = B[0], vy0 = B[1];
        const float vx1 = B[2], vy1 = B[3];
        const float vx2 = B[4], vy2 = B[5];
        const float vx3 = B[6], vy3 = B[7];
        const float cx = (vx0 + vx2) * 0.5f;
        const float cy = (vy0 + vy2) * 0.5f;

        #pragma unroll
        for (int k = 0; k < 9; k++) {
            const float px = P[2 * k];
            const float py = P[2 * k + 1];
            int crossings = 0;

            // edges (i, j=i-1 mod 4): (0,3),(1,0),(2,1),(3,2)
            #define SBL_EDGE(VX, VY, VXJ, VYJ)                                   \
                do {                                                             \
                    if (((VY) > py) != ((VYJ) > py)) {                           \
                        float xint = ((VXJ) - (VX)) * (py - (VY)) /              \
                                     ((VYJ) - (VY)) + (VX);                      \
                        if (px < xint) crossings ^= 1;                           \
                    }                                                            \
                } while (0)

            SBL_EDGE(vx0, vy0, vx3, vy3);
            SBL_EDGE(vx1, vy1, vx0, vy0);
            SBL_EDGE(vx2, vy2, vx1, vy1);
            SBL_EDGE(vx3, vy3, vx2, vy2);
            #undef SBL_EDGE

            if (!(crossings & 1)) {            // outside -> contributes
                const float dx = px - cx;
                const float dy = py - cy;
                dist_sum += 0.2f * sqrtf(dx * dx + dy * dy);
                cnt++;
            }
        }
        wp = (w[base + tid] > 0.0f) ? 1u : 0u;
    }

    // ---- Block reduction: warp shuffles then one atomic per block ----
    #pragma unroll
    for (int o = 16; o > 0; o >>= 1) {
        dist_sum += __shfl_down_sync(0xffffffffu, dist_sum, o);
        cnt      += __shfl_down_sync(0xffffffffu, cnt, o);
        wp       += __shfl_down_sync(0xffffffffu, wp, o);
    }

    __shared__ float        red_s[ROWS_PER_BLOCK / 32];
    __shared__ unsigned int red_c[ROWS_PER_BLOCK / 32];
    __shared__ unsigned int red_w[ROWS_PER_BLOCK / 32];

    const int wid  = tid >> 5;
    const int lane = tid & 31;
    if (lane == 0) { red_s[wid] = dist_sum; red_c[wid] = cnt; red_w[wid] = wp; }
    __syncthreads();

    if (wid == 0) {
        const int nw = ROWS_PER_BLOCK / 32;
        float        s = (lane < nw) ? red_s[lane] : 0.0f;
        unsigned int c = (lane < nw) ? red_c[lane] : 0u;
        unsigned int v = (lane < nw) ? red_w[lane] : 0u;
        #pragma unroll
        for (int o = 4; o > 0; o >>= 1) {
            s += __shfl_down_sync(0xffffffffu, s, o);
            c += __shfl_down_sync(0xffffffffu, c, o);
            v += __shfl_down_sync(0xffffffffu, v, o);
        }
        if (lane == 0) {
            atomicAdd(&g_sum, (double)s);
            atomicAdd(&g_cnt, c);
            atomicAdd(&g_wpos, v);
        }
    }
}

__global__ void sbl_final_kernel(float* __restrict__ out) {
    const double       s = g_sum;
    const unsigned int c = g_cnt;
    const unsigned int v = g_wpos;
    double loss_sb = 0.0;
    if (c > 0u) {
        unsigned int denom = c > 1u ? c : 1u;
        loss_sb = s / (double)denom;
    }
    const double avg_factor = (double)((float)v) + 1e-6;
    out[0] = (float)(loss_sb / avg_factor);
}

extern "C" void kernel_launch(void* const* d_in, const int* in_sizes, int n_in,
                              void* d_out, int out_size)
{
    const float* pts  = (const float*)d_in[0];
    const float* bbox = (const float*)d_in[1];
    const float* w    = (const float*)d_in[2];
    float* out        = (float*)d_out;

    const int N = in_sizes[0] / 18;
    const int grid = (N + ROWS_PER_BLOCK - 1) / ROWS_PER_BLOCK;

    sbl_init_kernel<<<1, 1>>>();
    sbl_main_kernel<<<grid, ROWS_PER_BLOCK>>>(pts, bbox, w, N);
    sbl_final_kernel<<<1, 1>>>(out);
}

// round 2
// speedup vs baseline: 1.8740x; 1.8740x over previous
#include <cuda_runtime.h>
#include <math.h>

// Global accumulators — zero-initialized at module load; the last block of each
// launch resets them to zero after producing the output, so every graph replay
// sees the same initial state (deterministic).
__device__ double       g_sum    = 0.0;
__device__ unsigned int g_cnt    = 0u;
__device__ unsigned int g_wpos   = 0u;
__device__ unsigned int g_arrive = 0u;

#define ROWS_PER_BLOCK 256

__device__ __forceinline__ float sqrt_approx(float x) {
    float r;
    asm("sqrt.approx.f32 %0, %1;" : "=f"(r) : "f"(x));
    return r;
}

__global__ void __launch_bounds__(ROWS_PER_BLOCK)
sbl_fused_kernel(const float* __restrict__ pts,
                 const float* __restrict__ bbox,
                 const float* __restrict__ w,
                 float* __restrict__ out,
                 int N, int nblocks)
{
    __shared__ float s_pts[ROWS_PER_BLOCK * 18];
    __shared__ float s_box[ROWS_PER_BLOCK * 8];

    const int tid   = threadIdx.x;
    const int base  = blockIdx.x * ROWS_PER_BLOCK;
    const int nrows = min(ROWS_PER_BLOCK, N - base);

    // ---- Coalesced staging: pts (float4) ----
    {
        const int tot = nrows * 18;
        const int n4  = tot >> 2;
        const float4* __restrict__ src4 = (const float4*)(pts + (size_t)base * 18);
        float4* dst4 = (float4*)s_pts;
        for (int i = tid; i < n4; i += ROWS_PER_BLOCK) dst4[i] = src4[i];
        for (int i = (n4 << 2) + tid; i < tot; i += ROWS_PER_BLOCK)
            s_pts[i] = pts[(size_t)base * 18 + i];
    }
    // ---- Coalesced staging: bbox (float4) ----
    {
        const int n4 = (nrows * 8) >> 2;
        const float4* __restrict__ src4 = (const float4*)(bbox + (size_t)base * 8);
        float4* dst4 = (float4*)s_box;
        for (int i = tid; i < n4; i += ROWS_PER_BLOCK) dst4[i] = src4[i];
    }
    __syncthreads();

    float        dist_sum = 0.0f;
    unsigned int cnt      = 0u;
    unsigned int wp       = 0u;

    if (tid < nrows) {
        const float* P = s_pts + tid * 18;
        const float* B = s_box + tid * 8;

        const float vx0 = B[0], vy0 = B[1];
        const float vx1 = B[2], vy1 = B[3];
        const float vx2 = B[4], vy2 = B[5];
        const float vx3 = B[6], vy3 = B[7];
        const float cx = (vx0 + vx2) * 0.5f;
        const float cy = (vy0 + vy2) * 0.5f;

        #pragma unroll
        for (int k = 0; k < 9; k++) {
            const float px = P[2 * k];
            const float py = P[2 * k + 1];
            unsigned int ins = 0u;   // parity of crossings

            // Branchless edge test:
            //   straddle = (vy>py) != (vyj>py)
            //   crossing = straddle && (sign(t)==sign(d)),
            //   d = vyj - vy,  t = (vxj-vx)*(py-vy) - (px-vx)*d
            #define SBL_EDGE(VX, VY, VXJ, VYJ)                                  \
                do {                                                            \
                    const bool  a = (VY)  > py;                                 \
                    const bool  b = (VYJ) > py;                                 \
                    const float d = (VYJ) - (VY);                               \
                    const float t = fmaf((VXJ) - (VX), py - (VY),               \
                                         -(px - (VX)) * d);                     \
                    const bool  c = (a != b) && ((t > 0.0f) == (d > 0.0f));     \
                    ins ^= (unsigned int)c;                                     \
                } while (0)

            SBL_EDGE(vx0, vy0, vx3, vy3);
            SBL_EDGE(vx1, vy1, vx0, vy0);
            SBL_EDGE(vx2, vy2, vx1, vy1);
            SBL_EDGE(vx3, vy3, vx2, vy2);
            #undef SBL_EDGE

            const float dx = px - cx;
            const float dy = py - cy;
            const float dist = 0.2f * sqrt_approx(fmaf(dx, dx, dy * dy));
            const float mask = ins ? 0.0f : 1.0f;    // outside contributes
            dist_sum = fmaf(dist, mask, dist_sum);
            cnt += (ins == 0u);
        }
        wp = (w[base + tid] > 0.0f) ? 1u : 0u;
    }

    // ---- Block reduction ----
    #pragma unroll
    for (int o = 16; o > 0; o >>= 1) {
        dist_sum += __shfl_down_sync(0xffffffffu, dist_sum, o);
        cnt      += __shfl_down_sync(0xffffffffu, cnt, o);
        wp       += __shfl_down_sync(0xffffffffu, wp, o);
    }

    __shared__ float        red_s[ROWS_PER_BLOCK / 32];
    __shared__ unsigned int red_c[ROWS_PER_BLOCK / 32];
    __shared__ unsigned int red_w[ROWS_PER_BLOCK / 32];
    __shared__ bool         s_is_last;

    const int wid  = tid >> 5;
    const int lane = tid & 31;
    if (lane == 0) { red_s[wid] = dist_sum; red_c[wid] = cnt; red_w[wid] = wp; }
    __syncthreads();

    if (tid < 32) {
        const int nw = ROWS_PER_BLOCK / 32;
        float        s = (lane < nw) ? red_s[lane] : 0.0f;
        unsigned int c = (lane < nw) ? red_c[lane] : 0u;
        unsigned int v = (lane < nw) ? red_w[lane] : 0u;
        #pragma unroll
        for (int o = 4; o > 0; o >>= 1) {
            s += __shfl_down_sync(0xffffffffu, s, o);
            c += __shfl_down_sync(0xffffffffu, c, o);
            v += __shfl_down_sync(0xffffffffu, v, o);
        }
        if (lane == 0) {
            atomicAdd(&g_sum, (double)s);
            atomicAdd(&g_cnt, c);
            atomicAdd(&g_wpos, v);
            __threadfence();
            const unsigned int ticket = atomicAdd(&g_arrive, 1u);
            s_is_last = (ticket == (unsigned int)(nblocks - 1));
        }
    }
    __syncthreads();

    // ---- Last block finalizes and resets state for the next replay ----
    if (s_is_last && tid == 0) {
        __threadfence();
        const double       S = atomicAdd(&g_sum, 0.0);
        const unsigned int C = atomicAdd(&g_cnt, 0u);
        const unsigned int V = atomicAdd(&g_wpos, 0u);

        double loss_sb = 0.0;
        if (C > 0u) {
            const unsigned int denom = (C > 1u) ? C : 1u;
            loss_sb = S / (double)denom;
        }
        const double avg_factor = (double)((float)V) + 1e-6;
        out[0] = (float)(loss_sb / avg_factor);

        // Reset for next graph replay (deterministic across calls)
        g_sum    = 0.0;
        g_cnt    = 0u;
        g_wpos   = 0u;
        g_arrive = 0u;
        __threadfence();
    }
}

extern "C" void kernel_launch(void* const* d_in, const int* in_sizes, int n_in,
                              void* d_out, int out_size)
{
    const float* pts  = (const float*)d_in[0];
    const float* bbox = (const float*)d_in[1];
    const float* w    = (const float*)d_in[2];
    float* out        = (float*)d_out;

    const int N    = in_sizes[0] / 18;
    const int grid = (N + ROWS_PER_BLOCK - 1) / ROWS_PER_BLOCK;

    sbl_fused_kernel<<<grid, ROWS_PER_BLOCK>>>(pts, bbox, w, out, N, grid);
}

// round 3
// speedup vs baseline: 2.2137x; 1.1813x over previous
#include <cuda_runtime.h>
#include <math.h>

// Zero-initialized at load; last block resets after finalize -> deterministic replays.
__device__ double       g_sum    = 0.0;
__device__ float        g_cnt    = 0.0f;
__device__ float        g_wpos   = 0.0f;
__device__ unsigned int g_arrive = 0u;

#define ROWS_PER_BLOCK 256

__device__ __forceinline__ float sqrt_approx(float x) {
    float r;
    asm("sqrt.approx.f32 %0, %1;" : "=f"(r) : "f"(x));
    return r;
}

__global__ void __launch_bounds__(ROWS_PER_BLOCK)
sbl_fused_kernel(const float* __restrict__ pts,
                 const float* __restrict__ bbox,
                 const float* __restrict__ w,
                 float* __restrict__ out,
                 int N, int nblocks)
{
    __shared__ float s_pts[ROWS_PER_BLOCK * 18];

    const int tid   = threadIdx.x;
    const int base  = blockIdx.x * ROWS_PER_BLOCK;
    const int nrows = min(ROWS_PER_BLOCK, N - base);

    // ---- Coalesced staging of pts into smem (float4) ----
    {
        const int tot = nrows * 18;
        const int n4  = tot >> 2;
        const float4* __restrict__ src4 = (const float4*)(pts + (size_t)base * 18);
        float4* dst4 = (float4*)s_pts;
        for (int i = tid; i < n4; i += ROWS_PER_BLOCK) dst4[i] = src4[i];
        for (int i = (n4 << 2) + tid; i < tot; i += ROWS_PER_BLOCK)
            s_pts[i] = pts[(size_t)base * 18 + i];
    }

    // ---- bbox: direct coalesced LDG.128 x2 (32B-aligned rows, no smem) ----
    float4 b0 = make_float4(0.f, 0.f, 0.f, 0.f);
    float4 b1 = make_float4(0.f, 1.f, 1.f, 0.f);   // degenerate-safe dummy
    float  wv = 0.0f;
    if (tid < nrows) {
        const float4* __restrict__ bb = (const float4*)(bbox + (size_t)base * 8);
        b0 = bb[2 * tid];
        b1 = bb[2 * tid + 1];
        wv = w[base + tid];
    }
    __syncthreads();

    float dist_sum = 0.0f;
    float cntf     = 0.0f;
    float wpf      = 0.0f;

    if (tid < nrows) {
        const float2* __restrict__ P2 = (const float2*)(s_pts + tid * 18);

        const float vx0 = b0.x, vy0 = b0.y;
        const float vx1 = b0.z, vy1 = b0.w;
        const float vx2 = b1.x, vy2 = b1.y;
        const float vx3 = b1.z, vy3 = b1.w;

        // Per-box edge constants (edge e: vertex i=e, prev j=(e+3)&3)
        const float ex0 = vx3 - vx0, dy0 = vy3 - vy0;   // (0,3)
        const float ex1 = vx0 - vx1, dy1 = vy0 - vy1;   // (1,0)
        const float ex2 = vx1 - vx2, dy2 = vy1 - vy2;   // (2,1)
        const float ex3 = vx2 - vx3, dy3 = vy2 - vy3;   // (3,2)

        const float cx = (vx0 + vx2) * 0.5f;
        const float cy = (vy0 + vy2) * 0.5f;

        #pragma unroll
        for (int k = 0; k < 9; k++) {
            const float2 p  = P2[k];
            const float  px = p.x;
            const float  py = p.y;

            // Signed offsets to each vertex (shared by edges)
            const float s0 = py - vy0, s1 = py - vy1, s2 = py - vy2, s3 = py - vy3;
            const float u0 = px - vx0, u1 = px - vx1, u2 = px - vx2, u3 = px - vx3;

            unsigned int ins = 0u;

            // crossing = (s_i * s_j < 0) && (t * d > 0),
            //   t = ex * s_i - u_i * d   (sign test replaces the division)
            {
                const float t = fmaf(ex0, s0, -u0 * dy0);
                const bool  c = (s0 * s3 < 0.0f) && (t * dy0 > 0.0f);
                ins ^= (unsigned int)c;
            }
            {
                const float t = fmaf(ex1, s1, -u1 * dy1);
                const bool  c = (s1 * s0 < 0.0f) && (t * dy1 > 0.0f);
                ins ^= (unsigned int)c;
            }
            {
                const float t = fmaf(ex2, s2, -u2 * dy2);
                const bool  c = (s2 * s1 < 0.0f) && (t * dy2 > 0.0f);
                ins ^= (unsigned int)c;
            }
            {
                const float t = fmaf(ex3, s3, -u3 * dy3);
                const bool  c = (s3 * s2 < 0.0f) && (t * dy3 > 0.0f);
                ins ^= (unsigned int)c;
            }

            const float dx = px - cx;
            const float dy = py - cy;
            const float s  = sqrt_approx(fmaf(dx, dx, dy * dy));  // 0.2 folded out
            const float m  = ins ? 0.0f : 1.0f;                   // outside mask
            dist_sum = fmaf(s, m, dist_sum);
            cntf    += m;
        }
        wpf = (wv > 0.0f) ? 1.0f : 0.0f;
    }

    // ---- Block reduction (all-float) ----
    #pragma unroll
    for (int o = 16; o > 0; o >>= 1) {
        dist_sum += __shfl_down_sync(0xffffffffu, dist_sum, o);
        cntf     += __shfl_down_sync(0xffffffffu, cntf, o);
        wpf      += __shfl_down_sync(0xffffffffu, wpf, o);
    }

    __shared__ float red_s[ROWS_PER_BLOCK / 32];
    __shared__ float red_c[ROWS_PER_BLOCK / 32];
    __shared__ float red_w[ROWS_PER_BLOCK / 32];
    __shared__ bool  s_is_last;

    const int wid  = tid >> 5;
    const int lane = tid & 31;
    if (lane == 0) { red_s[wid] = dist_sum; red_c[wid] = cntf; red_w[wid] = wpf; }
    __syncthreads();

    if (tid < 32) {
        const int nw = ROWS_PER_BLOCK / 32;
        float s = (lane < nw) ? red_s[lane] : 0.0f;
        float c = (lane < nw) ? red_c[lane] : 0.0f;
        float v = (lane < nw) ? red_w[lane] : 0.0f;
        #pragma unroll
        for (int o = 4; o > 0; o >>= 1) {
            s += __shfl_down_sync(0xffffffffu, s, o);
            c += __shfl_down_sync(0xffffffffu, c, o);
            v += __shfl_down_sync(0xffffffffu, v, o);
        }
        if (lane == 0) {
            atomicAdd(&g_sum,  (double)s);
            atomicAdd(&g_cnt,  c);
            atomicAdd(&g_wpos, v);
            __threadfence();
            const unsigned int ticket = atomicAdd(&g_arrive, 1u);
            s_is_last = (ticket == (unsigned int)(nblocks - 1));
        }
    }
    __syncthreads();

    if (s_is_last && tid == 0) {
        __threadfence();
        const double S = atomicAdd(&g_sum, 0.0);
        const float  C = g_cnt;
        const float  V = g_wpos;

        double loss_sb = 0.0;
        if (C > 0.0f) {
            const double denom = (C > 1.0f) ? (double)C : 1.0;
            loss_sb = 0.2 * S / denom;
        }
        const double avg_factor = (double)V + 1e-6;
        out[0] = (float)(loss_sb / avg_factor);

        g_sum    = 0.0;
        g_cnt    = 0.0f;
        g_wpos   = 0.0f;
        g_arrive = 0u;
        __threadfence();
    }
}

extern "C" void kernel_launch(void* const* d_in, const int* in_sizes, int n_in,
                              void* d_out, int out_size)
{
    const float* pts  = (const float*)d_in[0];
    const float* bbox = (const float*)d_in[1];
    const float* w    = (const float*)d_in[2];
    float* out        = (float*)d_out;

    const int N    = in_sizes[0] / 18;
    const int grid = (N + ROWS_PER_BLOCK - 1) / ROWS_PER_BLOCK;

    sbl_fused_kernel<<<grid, ROWS_PER_BLOCK>>>(pts, bbox, w, out, N, grid);
}

// round 5
// speedup vs baseline: 2.3770x; 1.0738x over previous
#include <cuda_runtime.h>
#include <math.h>
#include <stdint.h>

// Zero-initialized at load; last block resets after finalize -> deterministic replays.
__device__ double       g_sum    = 0.0;
__device__ unsigned int g_cnt    = 0u;
__device__ unsigned int g_wpos   = 0u;
__device__ unsigned int g_arrive = 0u;

#define ROWS_PER_BLOCK 256

__device__ __forceinline__ float sqrt_approx(float x) {
    float r;
    asm("sqrt.approx.f32 %0, %1;" : "=f"(r) : "f"(x));
    return r;
}

__device__ __forceinline__ uint64_t pk2(float lo, float hi) {
    uint64_t r; asm("mov.b64 %0, {%1, %2};" : "=l"(r) : "f"(lo), "f"(hi)); return r;
}
__device__ __forceinline__ void upk2(uint64_t v, float& lo, float& hi) {
    asm("mov.b64 {%0, %1}, %2;" : "=f"(lo), "=f"(hi) : "l"(v));
}
__device__ __forceinline__ uint64_t add2(uint64_t a, uint64_t b) {
    uint64_t r; asm("add.rn.f32x2 %0, %1, %2;" : "=l"(r) : "l"(a), "l"(b)); return r;
}
__device__ __forceinline__ uint64_t fma2(uint64_t a, uint64_t b, uint64_t c) {
    uint64_t r; asm("fma.rn.f32x2 %0, %1, %2, %3;" : "=l"(r) : "l"(a), "l"(b), "l"(c)); return r;
}

__global__ void __launch_bounds__(ROWS_PER_BLOCK)
sbl_fused_kernel(const float* __restrict__ pts,
                 const float* __restrict__ bbox,
                 const float* __restrict__ w,
                 float* __restrict__ out,
                 int N, int nblocks)
{
    __shared__ float s_pts[ROWS_PER_BLOCK * 18];

    const int tid   = threadIdx.x;
    const int base  = blockIdx.x * ROWS_PER_BLOCK;
    const int nrows = min(ROWS_PER_BLOCK, N - base);

    // ---- Coalesced staging of pts into smem (float4) ----
    {
        const int tot = nrows * 18;
        const int n4  = tot >> 2;
        const float4* __restrict__ src4 = (const float4*)(pts + (size_t)base * 18);
        float4* dst4 = (float4*)s_pts;
        for (int i = tid; i < n4; i += ROWS_PER_BLOCK) dst4[i] = src4[i];
        for (int i = (n4 << 2) + tid; i < tot; i += ROWS_PER_BLOCK)
            s_pts[i] = pts[(size_t)base * 18 + i];
    }

    // ---- bbox: direct coalesced LDG.128 x2 ----
    float4 b0 = make_float4(0.f, 0.f, 0.f, 0.f);
    float4 b1 = make_float4(0.f, 1.f, 1.f, 0.f);
    float  wv = 0.0f;
    if (tid < nrows) {
        const float4* __restrict__ bb = (const float4*)(bbox + (size_t)base * 8);
        b0 = bb[2 * tid];
        b1 = bb[2 * tid + 1];
        wv = w[base + tid];
    }
    __syncthreads();

    float        dist_sum = 0.0f;
    unsigned int cnt      = 0u;   // 9-point outside count
    unsigned int wp       = 0u;

    if (tid < nrows) {
        const float2* __restrict__ P2 = (const float2*)(s_pts + tid * 18);

        const float vx0 = b0.x, vy0 = b0.y;
        const float vx1 = b0.z, vy1 = b0.w;
        const float vx2 = b1.x, vy2 = b1.y;
        const float vx3 = b1.z, vy3 = b1.w;

        // Edges e: vertex i=e, prev j=(e+3)&3 : (0,3),(1,0),(2,1),(3,2)
        const float ex0 = vx3 - vx0, dyv0 = vy3 - vy0;
        const float ex1 = vx0 - vx1, dyv1 = vy0 - vy1;
        const float ex2 = vx1 - vx2, dyv2 = vy1 - vy2;
        const float ex3 = vx2 - vx3, dyv3 = vy2 - vy3;

        // t_e = ex_e*py - dy_e*px + c_e,  c_e = dy_e*vx_i - ex_e*vy_i
        const float c0 = fmaf(dyv0, vx0, -ex0 * vy0);
        const float c1 = fmaf(dyv1, vx1, -ex1 * vy1);
        const float c2 = fmaf(dyv2, vx2, -ex2 * vy2);
        const float c3 = fmaf(dyv3, vx3, -ex3 * vy3);

        // Packed per-box constants
        const uint64_t ex01  = pk2(ex0, ex1),    ex23  = pk2(ex2, ex3);
        const uint64_t ndy01 = pk2(-dyv0, -dyv1), ndy23 = pk2(-dyv2, -dyv3);
        const uint64_t c01   = pk2(c0, c1),      c23   = pk2(c2, c3);
        const uint64_t nvy01 = pk2(-vy0, -vy1),  nvy23 = pk2(-vy2, -vy3);

        // Sign-bit references: crossing needs sign(t)==sign(dy) <=> sign(t^(-dy))==1
        const int indy0 = __float_as_int(-dyv0);
        const int indy1 = __float_as_int(-dyv1);
        const int indy2 = __float_as_int(-dyv2);
        const int indy3 = __float_as_int(-dyv3);

        const float cx = (vx0 + vx2) * 0.5f;
        const float cy = (vy0 + vy2) * 0.5f;

        #pragma unroll
        for (int k = 0; k < 9; k++) {
            const float2 p  = P2[k];
            const float  px = p.x;
            const float  py = p.y;

            const uint64_t ppx = pk2(px, px);
            const uint64_t ppy = pk2(py, py);

            // s_i = py - vy_i  (2 packed adds)
            const uint64_t s01 = add2(ppy, nvy01);
            const uint64_t s23 = add2(ppy, nvy23);
            // t_e = ex*py + (-dy)*px + c  (4 packed FMAs)
            const uint64_t t01 = fma2(ex01, ppy, fma2(ndy01, ppx, c01));
            const uint64_t t23 = fma2(ex23, ppy, fma2(ndy23, ppx, c23));

            float s0, s1, s2, s3, t0, t1, t2, t3;
            upk2(s01, s0, s1); upk2(s23, s2, s3);
            upk2(t01, t0, t1); upk2(t23, t2, t3);

            const int is0 = __float_as_int(s0), is1 = __float_as_int(s1);
            const int is2 = __float_as_int(s2), is3 = __float_as_int(s3);

            // Parity of crossings lives in the sign bit of `ins`.
            int ins = 0;
            ins ^= (is0 ^ is3) & (__float_as_int(t0) ^ indy0);
            ins ^= (is1 ^ is0) & (__float_as_int(t1) ^ indy1);
            ins ^= (is2 ^ is1) & (__float_as_int(t2) ^ indy2);
            ins ^= (is3 ^ is2) & (__float_as_int(t3) ^ indy3);

            const float dx  = px - cx;
            const float dyc = py - cy;
            const float d   = sqrt_approx(fmaf(dx, dx, dyc * dyc)); // 0.2 folded out

            if (ins >= 0) {      // sign bit clear -> even crossings -> outside
                dist_sum += d;
                cnt++;
            }
        }
        wp = (wv > 0.0f) ? 1u : 0u;
    }

    // Fused integer counter: cnt in high bits, wp in low 10 bits.
    unsigned int comb = (cnt << 10) | wp;

    // ---- Block reduction: 2 shuffle chains instead of 3 ----
    #pragma unroll
    for (int o = 16; o > 0; o >>= 1) {
        dist_sum += __shfl_down_sync(0xffffffffu, dist_sum, o);
        comb     += __shfl_down_sync(0xffffffffu, comb, o);
    }

    __shared__ float        red_s[ROWS_PER_BLOCK / 32];
    __shared__ unsigned int red_c[ROWS_PER_BLOCK / 32];
    __shared__ bool         s_is_last;

    const int wid  = tid >> 5;
    const int lane = tid & 31;
    if (lane == 0) { red_s[wid] = dist_sum; red_c[wid] = comb; }
    __syncthreads();

    if (tid < 32) {
        const int nw = ROWS_PER_BLOCK / 32;
        float        s = (lane < nw) ? red_s[lane] : 0.0f;
        unsigned int c = (lane < nw) ? red_c[lane] : 0u;
        #pragma unroll
        for (int o = 4; o > 0; o >>= 1) {
            s += __shfl_down_sync(0xffffffffu, s, o);
            c += __shfl_down_sync(0xffffffffu, c, o);
        }
        if (lane == 0) {
            atomicAdd(&g_sum,  (double)s);
            atomicAdd(&g_cnt,  c >> 10);
            atomicAdd(&g_wpos, c & 1023u);
            __threadfence();
            const unsigned int ticket = atomicAdd(&g_arrive, 1u);
            s_is_last = (ticket == (unsigned int)(nblocks - 1));
        }
    }
    __syncthreads();

    if (s_is_last && tid == 0) {
        __threadfence();
        const double       S = atomicAdd(&g_sum, 0.0);
        const unsigned int C = g_cnt;
        const unsigned int V = g_wpos;

        double loss_sb = 0.0;
        if (C > 0u) {
            const unsigned int denom = (C > 1u) ? C : 1u;
            loss_sb = 0.2 * S / (double)denom;
        }
        const double avg_factor = (double)((float)V) + 1e-6;
        out[0] = (float)(loss_sb / avg_factor);

        g_sum    = 0.0;
        g_cnt    = 0u;
        g_wpos   = 0u;
        g_arrive = 0u;
        __threadfence();
    }
}

extern "C" void kernel_launch(void* const* d_in, const int* in_sizes, int n_in,
                              void* d_out, int out_size)
{
    const float* pts  = (const float*)d_in[0];
    const float* bbox = (const float*)d_in[1];
    const float* w    = (const float*)d_in[2];
    float* out        = (float*)d_out;

    const int N    = in_sizes[0] / 18;
    const int grid = (N + ROWS_PER_BLOCK - 1) / ROWS_PER_BLOCK;

    sbl_fused_kernel<<<grid, ROWS_PER_BLOCK>>>(pts, bbox, w, out, N, grid);
}

// round 6
// speedup vs baseline: 2.5439x; 1.0702x over previous
#include <cuda_runtime.h>
#include <math.h>
#include <stdint.h>

// Zero-initialized at load; last block resets after finalize -> deterministic replays.
__device__ double       g_sum    = 0.0;
__device__ unsigned int g_cnt    = 0u;
__device__ unsigned int g_wpos   = 0u;
__device__ unsigned int g_arrive = 0u;

#define ROWS_PER_BLOCK 256

__device__ __forceinline__ float sqrt_approx(float x) {
    float r;
    asm("sqrt.approx.f32 %0, %1;" : "=f"(r) : "f"(x));
    return r;
}

__global__ void __launch_bounds__(ROWS_PER_BLOCK)
sbl_fused_kernel(const float* __restrict__ pts,
                 const float* __restrict__ bbox,
                 const float* __restrict__ w,
                 float* __restrict__ out,
                 int N, int nblocks)
{
    __shared__ float s_pts[ROWS_PER_BLOCK * 18];

    const int tid   = threadIdx.x;
    const int base  = blockIdx.x * ROWS_PER_BLOCK;
    const int nrows = min(ROWS_PER_BLOCK, N - base);

    // ---- Coalesced staging of pts into smem (float4) ----
    {
        const int tot = nrows * 18;
        const int n4  = tot >> 2;
        const float4* __restrict__ src4 = (const float4*)(pts + (size_t)base * 18);
        float4* dst4 = (float4*)s_pts;
        for (int i = tid; i < n4; i += ROWS_PER_BLOCK) dst4[i] = src4[i];
        for (int i = (n4 << 2) + tid; i < tot; i += ROWS_PER_BLOCK)
            s_pts[i] = pts[(size_t)base * 18 + i];
    }

    // ---- bbox: direct coalesced LDG.128 x2 ----
    float4 b0 = make_float4(0.f, 0.f, 0.f, 0.f);
    float4 b1 = make_float4(0.f, 1.f, 1.f, 0.f);
    float  wv = 0.0f;
    if (tid < nrows) {
        const float4* __restrict__ bb = (const float4*)(bbox + (size_t)base * 8);
        b0 = bb[2 * tid];
        b1 = bb[2 * tid + 1];
        wv = w[base + tid];
    }
    __syncthreads();

    float        dist_sum = 0.0f;
    unsigned int cnt      = 0u;
    unsigned int wp       = 0u;

    if (tid < nrows) {
        const float2* __restrict__ P2 = (const float2*)(s_pts + tid * 18);

        const float vx0 = b0.x, vy0 = b0.y;
        const float vx1 = b0.z, vy1 = b0.w;
        const float vx2 = b1.x, vy2 = b1.y;
        const float vx3 = b1.z, vy3 = b1.w;

        // Directed edges for the fan decomposition:
        //   tri1 = (0->1, 1->2, 2->0),  tri2 = (0->2(= -2->0), 2->3, 3->0)
        // Line form: t_ab(p) = ex*py - dy*px + c,  ex = bx-ax, dy = by-ay,
        //            c = dy*ax - ex*ay   (sign of t = side of directed edge)
        #define SBL_EDGE_CONST(AX, AY, BX, BY, EX, DY, C)                      \
            const float EX = (BX) - (AX);                                      \
            const float DY = (BY) - (AY);                                      \
            const float C  = fmaf((DY), (AX), -(EX) * (AY));

        SBL_EDGE_CONST(vx0, vy0, vx1, vy1, ex01, dy01, c01)
        SBL_EDGE_CONST(vx1, vy1, vx2, vy2, ex12, dy12, c12)
        SBL_EDGE_CONST(vx2, vy2, vx0, vy0, ex20, dy20, c20)
        SBL_EDGE_CONST(vx2, vy2, vx3, vy3, ex23, dy23, c23)
        SBL_EDGE_CONST(vx3, vy3, vx0, vy0, ex30, dy30, c30)
        #undef SBL_EDGE_CONST

        const float ndy01 = -dy01, ndy12 = -dy12, ndy20 = -dy20;
        const float ndy23 = -dy23, ndy30 = -dy30;

        const float cx = (vx0 + vx2) * 0.5f;
        const float cy = (vy0 + vy2) * 0.5f;

        #pragma unroll
        for (int k = 0; k < 9; k++) {
            const float2 p  = P2[k];
            const float  px = p.x;
            const float  py = p.y;

            // 5 edge evaluations, 2 FMA each
            const int e01 = __float_as_int(fmaf(ex01, py, fmaf(ndy01, px, c01)));
            const int e12 = __float_as_int(fmaf(ex12, py, fmaf(ndy12, px, c12)));
            const int e20 = __float_as_int(fmaf(ex20, py, fmaf(ndy20, px, c20)));
            const int e23 = __float_as_int(fmaf(ex23, py, fmaf(ndy23, px, c23)));
            const int e30 = __float_as_int(fmaf(ex30, py, fmaf(ndy30, px, c30)));

            // Sign-bit logic (bitwise; only bit31 meaningful):
            //   in1 = 1 iff sign(e01)==sign(e12)==sign(e20)
            //   in2 = 1 iff sign(-e20)==sign(e23)==sign(e30)
            const int in1 = ~(e01 ^ e12) & ~(e01 ^ e20);
            const int in2 =  (e20 ^ e23) &  (e20 ^ e30);
            const int ins = in1 ^ in2;          // sign set -> inside (odd parity)

            const float dx  = px - cx;
            const float dyc = py - cy;
            const float d   = sqrt_approx(fmaf(dx, dx, dyc * dyc)); // 0.2 folded out

            // Branchless: outside (sign clear) contributes
            dist_sum += (ins >= 0) ? d : 0.0f;
            cnt      += ((unsigned int)(~ins)) >> 31;
        }
        wp = (wv > 0.0f) ? 1u : 0u;
    }

    // Fused integer counter: cnt in high bits, wp in low 10 bits.
    unsigned int comb = (cnt << 10) | wp;

    #pragma unroll
    for (int o = 16; o > 0; o >>= 1) {
        dist_sum += __shfl_down_sync(0xffffffffu, dist_sum, o);
        comb     += __shfl_down_sync(0xffffffffu, comb, o);
    }

    __shared__ float        red_s[ROWS_PER_BLOCK / 32];
    __shared__ unsigned int red_c[ROWS_PER_BLOCK / 32];
    __shared__ bool         s_is_last;

    const int wid  = tid >> 5;
    const int lane = tid & 31;
    if (lane == 0) { red_s[wid] = dist_sum; red_c[wid] = comb; }
    __syncthreads();

    if (tid < 32) {
        const int nw = ROWS_PER_BLOCK / 32;
        float        s = (lane < nw) ? red_s[lane] : 0.0f;
        unsigned int c = (lane < nw) ? red_c[lane] : 0u;
        #pragma unroll
        for (int o = 4; o > 0; o >>= 1) {
            s += __shfl_down_sync(0xffffffffu, s, o);
            c += __shfl_down_sync(0xffffffffu, c, o);
        }
        if (lane == 0) {
            atomicAdd(&g_sum,  (double)s);
            atomicAdd(&g_cnt,  c >> 10);
            atomicAdd(&g_wpos, c & 1023u);
            __threadfence();
            const unsigned int ticket = atomicAdd(&g_arrive, 1u);
            s_is_last = (ticket == (unsigned int)(nblocks - 1));
        }
    }
    __syncthreads();

    if (s_is_last && tid == 0) {
        __threadfence();
        const double       S = atomicAdd(&g_sum, 0.0);
        const unsigned int C = g_cnt;
        const unsigned int V = g_wpos;

        double loss_sb = 0.0;
        if (C > 0u) {
            const unsigned int denom = (C > 1u) ? C : 1u;
            loss_sb = 0.2 * S / (double)denom;
        }
        const double avg_factor = (double)((float)V) + 1e-6;
        out[0] = (float)(loss_sb / avg_factor);

        g_sum    = 0.0;
        g_cnt    = 0u;
        g_wpos   = 0u;
        g_arrive = 0u;
        __threadfence();
    }
}

extern "C" void kernel_launch(void* const* d_in, const int* in_sizes, int n_in,
                              void* d_out, int out_size)
{
    const float* pts  = (const float*)d_in[0];
    const float* bbox = (const float*)d_in[1];
    const float* w    = (const float*)d_in[2];
    float* out        = (float*)d_out;

    const int N    = in_sizes[0] / 18;
    const int grid = (N + ROWS_PER_BLOCK - 1) / ROWS_PER_BLOCK;

    sbl_fused_kernel<<<grid, ROWS_PER_BLOCK>>>(pts, bbox, w, out, N, grid);
}

// round 7
// speedup vs baseline: 2.9330x; 1.1530x over previous
#include <cuda_runtime.h>
#include <math.h>
#include <stdint.h>

// Zero-initialized at load; last block resets after finalize -> deterministic replays.
__device__ double       g_sum    = 0.0;
__device__ unsigned int g_cnt    = 0u;
__device__ unsigned int g_wpos   = 0u;
__device__ unsigned int g_arrive = 0u;

#define TILE_ROWS 256
#define TILES_PER_BLOCK 2
#define ROWS_PER_BLOCK (TILE_ROWS * TILES_PER_BLOCK)   // 512
#define TILE_FLOATS (TILE_ROWS * 18)                    // 4608

__device__ __forceinline__ float sqrt_approx(float x) {
    float r;
    asm("sqrt.approx.f32 %0, %1;" : "=f"(r) : "f"(x));
    return r;
}
__device__ __forceinline__ void cp_async16(uint32_t dst_smem, const void* src) {
    asm volatile("cp.async.cg.shared.global [%0], [%1], 16;"
                 :: "r"(dst_smem), "l"(src));
}
__device__ __forceinline__ void cp_async_commit() {
    asm volatile("cp.async.commit_group;");
}
template <int N>
__device__ __forceinline__ void cp_async_wait() {
    asm volatile("cp.async.wait_group %0;" :: "n"(N));
}
__device__ __forceinline__ uint32_t smem_u32(const void* p) {
    uint32_t a;
    asm("{ .reg .u64 t; cvta.to.shared.u64 t, %1; cvt.u32.u64 %0, t; }"
        : "=r"(a) : "l"(p));
    return a;
}

// Compute 9-point inside test + masked distance sum for one row.
__device__ __forceinline__ void sbl_row(const float* __restrict__ P,
                                        float4 b0, float4 b1,
                                        float& dist_sum, unsigned int& cnt)
{
    const float vx0 = b0.x, vy0 = b0.y;
    const float vx1 = b0.z, vy1 = b0.w;
    const float vx2 = b1.x, vy2 = b1.y;
    const float vx3 = b1.z, vy3 = b1.w;

    // Fan decomposition: tri1=(0->1,1->2,2->0), tri2=(-{2->0},2->3,3->0)
    #define SBL_EDGE_CONST(AX, AY, BX, BY, EX, NDY, C)                          \
        const float EX  = (BX) - (AX);                                          \
        const float NDY = (AY) - (BY);                                          \
        const float C   = fmaf(-(NDY), (AX), -(EX) * (AY));

    SBL_EDGE_CONST(vx0, vy0, vx1, vy1, ex01, ndy01, c01)
    SBL_EDGE_CONST(vx1, vy1, vx2, vy2, ex12, ndy12, c12)
    SBL_EDGE_CONST(vx2, vy2, vx0, vy0, ex20, ndy20, c20)
    SBL_EDGE_CONST(vx2, vy2, vx3, vy3, ex23, ndy23, c23)
    SBL_EDGE_CONST(vx3, vy3, vx0, vy0, ex30, ndy30, c30)
    #undef SBL_EDGE_CONST

    const float cx = (vx0 + vx2) * 0.5f;
    const float cy = (vy0 + vy2) * 0.5f;

    const float2* __restrict__ P2 = (const float2*)P;

    #pragma unroll
    for (int k = 0; k < 9; k++) {
        const float2 p  = P2[k];
        const float  px = p.x;
        const float  py = p.y;

        const int e01 = __float_as_int(fmaf(ex01, py, fmaf(ndy01, px, c01)));
        const int e12 = __float_as_int(fmaf(ex12, py, fmaf(ndy12, px, c12)));
        const int e20 = __float_as_int(fmaf(ex20, py, fmaf(ndy20, px, c20)));
        const int e23 = __float_as_int(fmaf(ex23, py, fmaf(ndy23, px, c23)));
        const int e30 = __float_as_int(fmaf(ex30, py, fmaf(ndy30, px, c30)));

        const int in1 = ~(e01 ^ e12) & ~(e01 ^ e20);
        const int in2 =  (e20 ^ e23) &  (e20 ^ e30);
        const int ins = in1 ^ in2;              // sign set -> inside

        const float dx  = px - cx;
        const float dyc = py - cy;
        const float d   = sqrt_approx(fmaf(dx, dx, dyc * dyc)); // 0.2 folded out

        dist_sum += (ins >= 0) ? d : 0.0f;
        cnt      += ((unsigned int)(~ins)) >> 31;
    }
}

__global__ void __launch_bounds__(TILE_ROWS)
sbl_fused_kernel(const float* __restrict__ pts,
                 const float* __restrict__ bbox,
                 const float* __restrict__ w,
                 float* __restrict__ out,
                 int N, int nblocks)
{
    __shared__ __align__(16) float s_pts[TILES_PER_BLOCK][TILE_FLOATS];

    const int tid   = threadIdx.x;
    const int base0 = blockIdx.x * ROWS_PER_BLOCK;              // tile 0 start
    const int base1 = base0 + TILE_ROWS;                        // tile 1 start
    const int nr0   = min(TILE_ROWS, max(0, N - base0));
    const int nr1   = min(TILE_ROWS, max(0, N - base1));

    // ---- Front-batched bbox/w LDGs for BOTH tiles (max MLP) ----
    float4 a0 = make_float4(0.f,0.f,0.f,0.f), a1 = make_float4(0.f,1.f,1.f,0.f);
    float4 d0 = make_float4(0.f,0.f,0.f,0.f), d1 = make_float4(0.f,1.f,1.f,0.f);
    float  wv0 = 0.0f, wv1 = 0.0f;
    if (tid < nr0) {
        const float4* __restrict__ bb = (const float4*)(bbox + (size_t)base0 * 8);
        a0 = bb[2 * tid]; a1 = bb[2 * tid + 1];
        wv0 = w[base0 + tid];
    }
    if (tid < nr1) {
        const float4* __restrict__ bb = (const float4*)(bbox + (size_t)base1 * 8);
        d0 = bb[2 * tid]; d1 = bb[2 * tid + 1];
        wv1 = w[base1 + tid];
    }

    // ---- Async staging of both tiles ----
    {
        const uint32_t sbase0 = smem_u32(&s_pts[0][0]);
        const int tot = nr0 * 18;
        const int n4  = tot >> 2;
        const float4* __restrict__ src4 = (const float4*)(pts + (size_t)base0 * 18);
        for (int i = tid; i < n4; i += TILE_ROWS)
            cp_async16(sbase0 + i * 16, src4 + i);
        for (int i = (n4 << 2) + tid; i < tot; i += TILE_ROWS)
            s_pts[0][i] = pts[(size_t)base0 * 18 + i];
    }
    cp_async_commit();
    if (nr1 > 0) {
        const uint32_t sbase1 = smem_u32(&s_pts[1][0]);
        const int tot = nr1 * 18;
        const int n4  = tot >> 2;
        const float4* __restrict__ src4 = (const float4*)(pts + (size_t)base1 * 18);
        for (int i = tid; i < n4; i += TILE_ROWS)
            cp_async16(sbase1 + i * 16, src4 + i);
        for (int i = (n4 << 2) + tid; i < tot; i += TILE_ROWS)
            s_pts[1][i] = pts[(size_t)base1 * 18 + i];
    }
    cp_async_commit();

    float        dist_sum = 0.0f;
    unsigned int cnt      = 0u;
    unsigned int wp       = 0u;

    // ---- Tile 0 (tile 1's loads still in flight) ----
    cp_async_wait<1>();
    __syncthreads();
    if (tid < nr0) {
        sbl_row(&s_pts[0][tid * 18], a0, a1, dist_sum, cnt);
        wp += (wv0 > 0.0f) ? 1u : 0u;
    }

    // ---- Tile 1 ----
    cp_async_wait<0>();
    __syncthreads();
    if (tid < nr1) {
        sbl_row(&s_pts[1][tid * 18], d0, d1, dist_sum, cnt);
        wp += (wv1 > 0.0f) ? 1u : 0u;
    }

    // ---- Single epilogue per 512 rows ----
    unsigned int comb = (cnt << 10) | wp;   // cnt<=18 -> block sum <= 9216 ok

    #pragma unroll
    for (int o = 16; o > 0; o >>= 1) {
        dist_sum += __shfl_down_sync(0xffffffffu, dist_sum, o);
        comb     += __shfl_down_sync(0xffffffffu, comb, o);
    }

    __shared__ float        red_s[TILE_ROWS / 32];
    __shared__ unsigned int red_c[TILE_ROWS / 32];
    __shared__ bool         s_is_last;

    const int wid  = tid >> 5;
    const int lane = tid & 31;
    if (lane == 0) { red_s[wid] = dist_sum; red_c[wid] = comb; }
    __syncthreads();

    if (tid < 32) {
        const int nw = TILE_ROWS / 32;
        float        s = (lane < nw) ? red_s[lane] : 0.0f;
        unsigned int c = (lane < nw) ? red_c[lane] : 0u;
        #pragma unroll
        for (int o = 4; o > 0; o >>= 1) {
            s += __shfl_down_sync(0xffffffffu, s, o);
            c += __shfl_down_sync(0xffffffffu, c, o);
        }
        if (lane == 0) {
            atomicAdd(&g_sum,  (double)s);
            atomicAdd(&g_cnt,  c >> 10);
            atomicAdd(&g_wpos, c & 1023u);
            __threadfence();
            const unsigned int ticket = atomicAdd(&g_arrive, 1u);
            s_is_last = (ticket == (unsigned int)(nblocks - 1));
        }
    }
    __syncthreads();

    if (s_is_last && tid == 0) {
        __threadfence();
        const double       S = atomicAdd(&g_sum, 0.0);
        const unsigned int C = g_cnt;
        const unsigned int V = g_wpos;

        double loss_sb = 0.0;
        if (C > 0u) {
            const unsigned int denom = (C > 1u) ? C : 1u;
            loss_sb = 0.2 * S / (double)denom;
        }
        const double avg_factor = (double)((float)V) + 1e-6;
        out[0] = (float)(loss_sb / avg_factor);

        g_sum    = 0.0;
        g_cnt    = 0u;
        g_wpos   = 0u;
        g_arrive = 0u;
        __threadfence();
    }
}

extern "C" void kernel_launch(void* const* d_in, const int* in_sizes, int n_in,
                              void* d_out, int out_size)
{
    const float* pts  = (const float*)d_in[0];
    const float* bbox = (const float*)d_in[1];
    const float* w    = (const float*)d_in[2];
    float* out        = (float*)d_out;

    const int N    = in_sizes[0] / 18;
    const int grid = (N + ROWS_PER_BLOCK - 1) / ROWS_PER_BLOCK;

    sbl_fused_kernel<<<grid, TILE_ROWS>>>(pts, bbox, w, out, N, grid);
}

// round 9
// speedup vs baseline: 3.0446x; 1.0381x over previous
#include <cuda_runtime.h>
#include <math.h>
#include <stdint.h>

// Zero-initialized at load; last block resets after finalize -> deterministic replays.
__device__ double       g_sum    = 0.0;
__device__ unsigned int g_cnt    = 0u;
__device__ unsigned int g_wpos   = 0u;
__device__ unsigned int g_arrive = 0u;

#define TILE_ROWS 256
#define TILE_FLOATS (TILE_ROWS * 18)    // 4608 floats = 18 KB
#define MAX_BLOCKS 740                  // 148 SMs * 5 resident blocks

__device__ __forceinline__ float sqrt_approx(float x) {
    float r;
    asm("sqrt.approx.f32 %0, %1;" : "=f"(r) : "f"(x));
    return r;
}
__device__ __forceinline__ void cp_async16(uint32_t dst_smem, const void* src) {
    asm volatile("cp.async.cg.shared.global [%0], [%1], 16;"
                 :: "r"(dst_smem), "l"(src));
}
__device__ __forceinline__ void cp_async_commit() {
    asm volatile("cp.async.commit_group;");
}
template <int K>
__device__ __forceinline__ void cp_async_wait() {
    asm volatile("cp.async.wait_group %0;" :: "n"(K));
}
__device__ __forceinline__ uint32_t smem_u32(const void* p) {
    uint32_t a;
    asm("{ .reg .u64 t; cvta.to.shared.u64 t, %1; cvt.u32.u64 %0, t; }"
        : "=r"(a) : "l"(p));
    return a;
}

__device__ __forceinline__ void sbl_row(const float* __restrict__ P,
                                        float4 b0, float4 b1,
                                        float& dist_sum, unsigned int& cnt)
{
    const float vx0 = b0.x, vy0 = b0.y;
    const float vx1 = b0.z, vy1 = b0.w;
    const float vx2 = b1.x, vy2 = b1.y;
    const float vx3 = b1.z, vy3 = b1.w;

    // Fan decomposition: tri1=(0->1,1->2,2->0), tri2=(-{2->0},2->3,3->0)
    #define SBL_EDGE_CONST(AX, AY, BX, BY, EX, NDY, C)                          \
        const float EX  = (BX) - (AX);                                          \
        const float NDY = (AY) - (BY);                                          \
        const float C   = fmaf(-(NDY), (AX), -(EX) * (AY));

    SBL_EDGE_CONST(vx0, vy0, vx1, vy1, ex01, ndy01, c01)
    SBL_EDGE_CONST(vx1, vy1, vx2, vy2, ex12, ndy12, c12)
    SBL_EDGE_CONST(vx2, vy2, vx0, vy0, ex20, ndy20, c20)
    SBL_EDGE_CONST(vx2, vy2, vx3, vy3, ex23, ndy23, c23)
    SBL_EDGE_CONST(vx3, vy3, vx0, vy0, ex30, ndy30, c30)
    #undef SBL_EDGE_CONST

    const float cx = (vx0 + vx2) * 0.5f;
    const float cy = (vy0 + vy2) * 0.5f;

    const float2* __restrict__ P2 = (const float2*)P;

    #pragma unroll
    for (int k = 0; k < 9; k++) {
        const float2 p  = P2[k];
        const float  px = p.x;
        const float  py = p.y;

        const int e01 = __float_as_int(fmaf(ex01, py, fmaf(ndy01, px, c01)));
        const int e12 = __float_as_int(fmaf(ex12, py, fmaf(ndy12, px, c12)));
        const int e20 = __float_as_int(fmaf(ex20, py, fmaf(ndy20, px, c20)));
        const int e23 = __float_as_int(fmaf(ex23, py, fmaf(ndy23, px, c23)));
        const int e30 = __float_as_int(fmaf(ex30, py, fmaf(ndy30, px, c30)));

        const int in1 = ~(e01 ^ e12) & ~(e01 ^ e20);
        const int in2 =  (e20 ^ e23) &  (e20 ^ e30);
        const int ins = in1 ^ in2;              // sign set -> inside

        const float dx  = px - cx;
        const float dyc = py - cy;
        const float d   = sqrt_approx(fmaf(dx, dx, dyc * dyc)); // 0.2 folded out

        dist_sum += (ins >= 0) ? d : 0.0f;
        cnt      += ((unsigned int)(~ins)) >> 31;
    }
}

__global__ void __launch_bounds__(TILE_ROWS)
sbl_fused_kernel(const float* __restrict__ pts,
                 const float* __restrict__ bbox,
                 const float* __restrict__ w,
                 float* __restrict__ out,
                 int N, int ntiles, int nblocks)
{
    __shared__ __align__(16) float s_pts[2][TILE_FLOATS];

    const int tid = threadIdx.x;
    const int bid = blockIdx.x;

    // ---- Stage helper (partial tiles handled) ----
    #define SBL_STAGE(BUF, TILE)                                                \
        do {                                                                    \
            const int _base = (TILE) * TILE_ROWS;                               \
            const int _nr   = min(TILE_ROWS, N - _base);                        \
            const int _tot  = _nr * 18;                                         \
            const int _n4   = _tot >> 2;                                        \
            const uint32_t _sb = smem_u32(&s_pts[BUF][0]);                      \
            const float4* __restrict__ _s4 =                                    \
                (const float4*)(pts + (size_t)_base * 18);                      \
            for (int _i = tid; _i < _n4; _i += TILE_ROWS)                       \
                cp_async16(_sb + _i * 16, _s4 + _i);                            \
            for (int _i = (_n4 << 2) + tid; _i < _tot; _i += TILE_ROWS)         \
                s_pts[BUF][_i] = pts[(size_t)_base * 18 + _i];                  \
        } while (0)

    // ---- Prologue: stage first tile ----
    if (bid < ntiles) SBL_STAGE(0, bid);
    cp_async_commit();

    float        dist_sum = 0.0f;
    unsigned int cnt      = 0u;
    unsigned int wp       = 0u;

    int buf = 0;
    for (int t = bid; t < ntiles; t += nblocks, buf ^= 1) {
        const int base = t * TILE_ROWS;
        const int nr   = min(TILE_ROWS, N - base);

        // Issue bbox/w loads for this tile early (latency hides under wait)
        float4 b0 = make_float4(0.f,0.f,0.f,0.f);
        float4 b1 = make_float4(0.f,1.f,1.f,0.f);
        float  wv = 0.0f;
        if (tid < nr) {
            const float4* __restrict__ bb = (const float4*)(bbox + (size_t)base * 8);
            b0 = bb[2 * tid];
            b1 = bb[2 * tid + 1];
            wv = w[base + tid];
        }

        // Protect the other buffer (rewritten below) from the previous
        // iteration's readers.
        __syncthreads();

        const int tn = t + nblocks;
        if (tn < ntiles) SBL_STAGE(buf ^ 1, tn);
        cp_async_commit();

        cp_async_wait<1>();     // current tile's group is complete
        __syncthreads();

        if (tid < nr) {
            sbl_row(&s_pts[buf][tid * 18], b0, b1, dist_sum, cnt);
            wp += (wv > 0.0f) ? 1u : 0u;
        }
    }
    #undef SBL_STAGE

    // ---- One epilogue per block. cnt<=9*tiles_per_block, wp<=tiles_per_block.
    // Block sums: cnt <= 256*9*6=13824 < 65536, wp <= 1536 < 65536.
    unsigned int comb = (cnt << 16) | wp;

    #pragma unroll
    for (int o = 16; o > 0; o >>= 1) {
        dist_sum += __shfl_down_sync(0xffffffffu, dist_sum, o);
        comb     += __shfl_down_sync(0xffffffffu, comb, o);
    }

    __shared__ float        red_s[TILE_ROWS / 32];
    __shared__ unsigned int red_c[TILE_ROWS / 32];
    __shared__ bool         s_is_last;

    const int wid  = tid >> 5;
    const int lane = tid & 31;
    if (lane == 0) { red_s[wid] = dist_sum; red_c[wid] = comb; }
    __syncthreads();

    if (tid < 32) {
        const int nw = TILE_ROWS / 32;
        float        s = (lane < nw) ? red_s[lane] : 0.0f;
        unsigned int c = (lane < nw) ? red_c[lane] : 0u;
        #pragma unroll
        for (int o = 4; o > 0; o >>= 1) {
            s += __shfl_down_sync(0xffffffffu, s, o);
            c += __shfl_down_sync(0xffffffffu, c, o);
        }
        if (lane == 0) {
            atomicAdd(&g_sum,  (double)s);
            atomicAdd(&g_cnt,  c >> 16);
            atomicAdd(&g_wpos, c & 0xFFFFu);
            __threadfence();
            const unsigned int ticket = atomicAdd(&g_arrive, 1u);
            s_is_last = (ticket == (unsigned int)(nblocks - 1));
        }
    }
    __syncthreads();

    if (s_is_last && tid == 0) {
        __threadfence();
        const double       S = atomicAdd(&g_sum, 0.0);
        const unsigned int C = g_cnt;
        const unsigned int V = g_wpos;

        double loss_sb = 0.0;
        if (C > 0u) {
            const unsigned int denom = (C > 1u) ? C : 1u;
            loss_sb = 0.2 * S / (double)denom;
        }
        const double avg_factor = (double)((float)V) + 1e-6;
        out[0] = (float)(loss_sb / avg_factor);

        g_sum    = 0.0;
        g_cnt    = 0u;
        g_wpos   = 0u;
        g_arrive = 0u;
        __threadfence();
    }
}

extern "C" void kernel_launch(void* const* d_in, const int* in_sizes, int n_in,
                              void* d_out, int out_size)
{
    const float* pts  = (const float*)d_in[0];
    const float* bbox = (const float*)d_in[1];
    const float* w    = (const float*)d_in[2];
    float* out        = (float*)d_out;

    const int N      = in_sizes[0] / 18;
    const int ntiles = (N + TILE_ROWS - 1) / TILE_ROWS;
    const int grid   = (ntiles < MAX_BLOCKS) ? ntiles : MAX_BLOCKS;

    sbl_fused_kernel<<<grid, TILE_ROWS>>>(pts, bbox, w, out, N, ntiles, grid);
}

// round 10
// speedup vs baseline: 3.3048x; 1.0855x over previous
#include <cuda_runtime.h>
#include <math.h>
#include <stdint.h>

// Zero-initialized at load; last block resets after finalize -> deterministic replays.
__device__ double       g_sum    = 0.0;
__device__ unsigned int g_cnt    = 0u;
__device__ unsigned int g_wpos   = 0u;
__device__ unsigned int g_arrive = 0u;

#define TILE_ROWS 256
#define TILE_FLOATS (TILE_ROWS * 18)    // 4608 floats = 18432 B
#define MAX_BLOCKS 740                  // 148 SMs * 5 resident blocks

__device__ __forceinline__ float sqrt_approx(float x) {
    float r;
    asm("sqrt.approx.f32 %0, %1;" : "=f"(r) : "f"(x));
    return r;
}
__device__ __forceinline__ uint32_t smem_u32(const void* p) {
    uint32_t a;
    asm("{ .reg .u64 t; cvta.to.shared.u64 t, %1; cvt.u32.u64 %0, t; }"
        : "=r"(a) : "l"(p));
    return a;
}
__device__ __forceinline__ void mbar_init(uint32_t mbar, uint32_t count) {
    asm volatile("mbarrier.init.shared.b64 [%0], %1;" :: "r"(mbar), "r"(count) : "memory");
}
__device__ __forceinline__ void mbar_expect_tx(uint32_t mbar, uint32_t bytes) {
    asm volatile("mbarrier.arrive.expect_tx.shared.b64 _, [%0], %1;"
                 :: "r"(mbar), "r"(bytes) : "memory");
}
__device__ __forceinline__ void bulk_g2s(uint32_t dst, const void* src,
                                         uint32_t bytes, uint32_t mbar) {
    asm volatile("cp.async.bulk.shared::cta.global.mbarrier::complete_tx::bytes "
                 "[%0], [%1], %2, [%3];"
                 :: "r"(dst), "l"(src), "r"(bytes), "r"(mbar) : "memory");
}
__device__ __forceinline__ void mbar_wait(uint32_t mbar, uint32_t parity) {
    uint32_t done;
    asm volatile(
        "{\n\t.reg .pred p;\n\t"
        "mbarrier.try_wait.parity.acquire.cta.shared::cta.b64 p, [%1], %2;\n\t"
        "selp.b32 %0, 1, 0, p;\n\t}"
        : "=r"(done) : "r"(mbar), "r"(parity) : "memory");
    if (!done) {
        asm volatile(
            "{\n\t.reg .pred P1;\n\t"
            "WAIT_LOOP_%=:\n\t"
            "mbarrier.try_wait.parity.acquire.cta.shared::cta.b64 P1, [%0], %1, 0x989680;\n\t"
            "@P1 bra.uni WAIT_DONE_%=;\n\t"
            "bra.uni WAIT_LOOP_%=;\n\t"
            "WAIT_DONE_%=:\n\t}"
            :: "r"(mbar), "r"(parity) : "memory");
    }
}

__device__ __forceinline__ void sbl_row(const float* __restrict__ P,
                                        float4 b0, float4 b1,
                                        float& dist_sum, unsigned int& cnt)
{
    const float vx0 = b0.x, vy0 = b0.y;
    const float vx1 = b0.z, vy1 = b0.w;
    const float vx2 = b1.x, vy2 = b1.y;
    const float vx3 = b1.z, vy3 = b1.w;

    // Fan decomposition: tri1=(0->1,1->2,2->0), tri2=(-{2->0},2->3,3->0)
    #define SBL_EDGE_CONST(AX, AY, BX, BY, EX, NDY, C)                          \
        const float EX  = (BX) - (AX);                                          \
        const float NDY = (AY) - (BY);                                          \
        const float C   = fmaf(-(NDY), (AX), -(EX) * (AY));

    SBL_EDGE_CONST(vx0, vy0, vx1, vy1, ex01, ndy01, c01)
    SBL_EDGE_CONST(vx1, vy1, vx2, vy2, ex12, ndy12, c12)
    SBL_EDGE_CONST(vx2, vy2, vx0, vy0, ex20, ndy20, c20)
    SBL_EDGE_CONST(vx2, vy2, vx3, vy3, ex23, ndy23, c23)
    SBL_EDGE_CONST(vx3, vy3, vx0, vy0, ex30, ndy30, c30)
    #undef SBL_EDGE_CONST

    const float cx = (vx0 + vx2) * 0.5f;
    const float cy = (vy0 + vy2) * 0.5f;

    const float2* __restrict__ P2 = (const float2*)P;

    #pragma unroll
    for (int k = 0; k < 9; k++) {
        const float2 p  = P2[k];
        const float  px = p.x;
        const float  py = p.y;

        const int e01 = __float_as_int(fmaf(ex01, py, fmaf(ndy01, px, c01)));
        const int e12 = __float_as_int(fmaf(ex12, py, fmaf(ndy12, px, c12)));
        const int e20 = __float_as_int(fmaf(ex20, py, fmaf(ndy20, px, c20)));
        const int e23 = __float_as_int(fmaf(ex23, py, fmaf(ndy23, px, c23)));
        const int e30 = __float_as_int(fmaf(ex30, py, fmaf(ndy30, px, c30)));

        const int in1 = ~(e01 ^ e12) & ~(e01 ^ e20);
        const int in2 =  (e20 ^ e23) &  (e20 ^ e30);
        const int ins = in1 ^ in2;              // sign set -> inside

        const float dx  = px - cx;
        const float dyc = py - cy;
        const float d   = sqrt_approx(fmaf(dx, dx, dyc * dyc)); // 0.2 folded out

        dist_sum += (ins >= 0) ? d : 0.0f;
        cnt      += ((unsigned int)(~ins)) >> 31;
    }
}

__global__ void __launch_bounds__(TILE_ROWS)
sbl_fused_kernel(const float* __restrict__ pts,
                 const float* __restrict__ bbox,
                 const float* __restrict__ w,
                 float* __restrict__ out,
                 int N, int ntiles, int nblocks)
{
    __shared__ __align__(16) float    s_pts[2][TILE_FLOATS];
    __shared__ __align__(8)  uint64_t s_mbar[2];

    const int tid = threadIdx.x;
    const int bid = blockIdx.x;

    const uint32_t mbar0 = smem_u32(&s_mbar[0]);
    const uint32_t mbar1 = smem_u32(&s_mbar[1]);
    const uint32_t sb0   = smem_u32(&s_pts[0][0]);
    const uint32_t sb1   = smem_u32(&s_pts[1][0]);

    if (tid == 0) {
        mbar_init(mbar0, 1u);
        mbar_init(mbar1, 1u);
    }
    __syncthreads();

    // ---- Stage one tile with a single bulk copy (thread 0). Tail bytes
    // (size not multiple of 16) are copied with plain stores; they are
    // ordered for consumers by the __syncthreads preceding each compute.
    #define SBL_STAGE(SBASE, MBAR, TILE)                                        \
        do {                                                                    \
            const int      _base  = (TILE) * TILE_ROWS;                         \
            const int      _nr    = min(TILE_ROWS, N - _base);                  \
            const uint32_t _bytes = (uint32_t)(_nr * 18) * 4u;                  \
            const uint32_t _b16   = _bytes & ~15u;                              \
            const char*    _src   = (const char*)(pts + (size_t)_base * 18);    \
            mbar_expect_tx((MBAR), _b16);                                       \
            bulk_g2s((SBASE), _src, _b16, (MBAR));                              \
            for (uint32_t _o = _b16; _o < _bytes; _o += 4u)                     \
                *(float*)((char*)s_pts + ((SBASE) - sb0) + _o) =                \
                    *(const float*)(_src + _o);                                 \
        } while (0)

    // ---- Prologue: stage first tile into buffer 0 ----
    if (tid == 0 && bid < ntiles) SBL_STAGE(sb0, mbar0, bid);

    float        dist_sum = 0.0f;
    unsigned int cnt      = 0u;
    unsigned int wp       = 0u;

    int      buf = 0;
    uint32_t ph0 = 0u, ph1 = 0u;

    for (int t = bid; t < ntiles; t += nblocks, buf ^= 1) {
        const int base = t * TILE_ROWS;
        const int nr   = min(TILE_ROWS, N - base);

        // bbox/w loads issued early; latency hides under the mbarrier wait
        float4 b0 = make_float4(0.f,0.f,0.f,0.f);
        float4 b1 = make_float4(0.f,1.f,1.f,0.f);
        float  wv = 0.0f;
        if (tid < nr) {
            const float4* __restrict__ bb = (const float4*)(bbox + (size_t)base * 8);
            b0 = bb[2 * tid];
            b1 = bb[2 * tid + 1];
            wv = w[base + tid];
        }

        // All threads done reading the other buffer from the previous iter.
        __syncthreads();

        const int tn = t + nblocks;
        if (tid == 0 && tn < ntiles) {
            if (buf == 0) SBL_STAGE(sb1, mbar1, tn);
            else          SBL_STAGE(sb0, mbar0, tn);
        }

        // Wait for the current buffer's bulk copy.
        if (buf == 0) { mbar_wait(mbar0, ph0); ph0 ^= 1u; }
        else          { mbar_wait(mbar1, ph1); ph1 ^= 1u; }

        if (tid < nr) {
            sbl_row(&s_pts[buf][tid * 18], b0, b1, dist_sum, cnt);
            wp += (wv > 0.0f) ? 1u : 0u;
        }
    }
    #undef SBL_STAGE

    // ---- One epilogue per block (cnt block-sum <= 13824, wp <= 1536) ----
    unsigned int comb = (cnt << 16) | wp;

    #pragma unroll
    for (int o = 16; o > 0; o >>= 1) {
        dist_sum += __shfl_down_sync(0xffffffffu, dist_sum, o);
        comb     += __shfl_down_sync(0xffffffffu, comb, o);
    }

    __shared__ float        red_s[TILE_ROWS / 32];
    __shared__ unsigned int red_c[TILE_ROWS / 32];
    __shared__ bool         s_is_last;

    const int wid  = tid >> 5;
    const int lane = tid & 31;
    if (lane == 0) { red_s[wid] = dist_sum; red_c[wid] = comb; }
    __syncthreads();

    if (tid < 32) {
        const int nw = TILE_ROWS / 32;
        float        s = (lane < nw) ? red_s[lane] : 0.0f;
        unsigned int c = (lane < nw) ? red_c[lane] : 0u;
        #pragma unroll
        for (int o = 4; o > 0; o >>= 1) {
            s += __shfl_down_sync(0xffffffffu, s, o);
            c += __shfl_down_sync(0xffffffffu, c, o);
        }
        if (lane == 0) {
            atomicAdd(&g_sum,  (double)s);
            atomicAdd(&g_cnt,  c >> 16);
            atomicAdd(&g_wpos, c & 0xFFFFu);
            __threadfence();
            const unsigned int ticket = atomicAdd(&g_arrive, 1u);
            s_is_last = (ticket == (unsigned int)(nblocks - 1));
        }
    }
    __syncthreads();

    if (s_is_last && tid == 0) {
        __threadfence();
        const double       S = atomicAdd(&g_sum, 0.0);
        const unsigned int C = g_cnt;
        const unsigned int V = g_wpos;

        double loss_sb = 0.0;
        if (C > 0u) {
            const unsigned int denom = (C > 1u) ? C : 1u;
            loss_sb = 0.2 * S / (double)denom;
        }
        const double avg_factor = (double)((float)V) + 1e-6;
        out[0] = (float)(loss_sb / avg_factor);

        g_sum    = 0.0;
        g_cnt    = 0u;
        g_wpos   = 0u;
        g_arrive = 0u;
        __threadfence();
    }
}

extern "C" void kernel_launch(void* const* d_in, const int* in_sizes, int n_in,
                              void* d_out, int out_size)
{
    const float* pts  = (const float*)d_in[0];
    const float* bbox = (const float*)d_in[1];
    const float* w    = (const float*)d_in[2];
    float* out        = (float*)d_out;

    const int N      = in_sizes[0] / 18;
    const int ntiles = (N + TILE_ROWS - 1) / TILE_ROWS;
    const int grid   = (ntiles < MAX_BLOCKS) ? ntiles : MAX_BLOCKS;

    sbl_fused_kernel<<<grid, TILE_ROWS>>>(pts, bbox, w, out, N, ntiles, grid);
}